// round 14
// baseline (speedup 1.0000x reference)
#include <cuda_runtime.h>
#include <cuda_bf16.h>
#include <cstdint>

#define BATCH 8
#define NPTS  4096
#define CFEAT 128
#define NPOINT 1024
#define NSAMPLE 32
#define COUT  256
#define CIN   131   // 3 + 128
#define NCELL 1000  // 10x10x10
#define SENT  0x7FFFFFFF

typedef unsigned long long u64;

// ---------------- scratch (device globals; no allocation allowed) ----------------
__device__ float  g_P[BATCH * NPTS * COUT];          // per-point feature GEMM result
__device__ float  g_cent[BATCH * NPOINT * 3];        // new_xyz copy for device use
__device__ float  g_scale[CIN];                      // gamma / sqrt(var+eps)
__device__ float  g_Wt[CIN * COUT];                  // W transposed
__device__ int    g_cellStart[BATCH * (NCELL + 1)];  // bin CSR offsets
__device__ float4 g_xyzBin[BATCH * NPTS];            // (x,y,z,orig_idx) in binned order

// ---------------- packed f32x2 helpers (bit-identical to scalar rn ops) ----------------
__device__ __forceinline__ u64 f2_add(u64 a, u64 b) {
    u64 r; asm("add.rn.f32x2 %0,%1,%2;" : "=l"(r) : "l"(a), "l"(b)); return r;
}
__device__ __forceinline__ u64 f2_mul(u64 a, u64 b) {
    u64 r; asm("mul.rn.f32x2 %0,%1,%2;" : "=l"(r) : "l"(a), "l"(b)); return r;
}
__device__ __forceinline__ u64 f2_pack(float lo, float hi) {
    u64 r; asm("mov.b64 %0,{%1,%2};" : "=l"(r) : "f"(lo), "f"(hi)); return r;
}
__device__ __forceinline__ void f2_unpack(u64 v, float& lo, float& hi) {
    asm("mov.b64 {%0,%1},%2;" : "=f"(lo), "=f"(hi) : "l"(v));
}

// ---------------- bin points into grid + (folded) init of g_Wt/g_scale ----------------
__global__ void __launch_bounds__(1024) bin_kernel(const float* __restrict__ xyz,
                                                   const float* __restrict__ W,
                                                   const float* __restrict__ gamma,
                                                   const float* __restrict__ var) {
    __shared__ int hist[NCELL];
    __shared__ int off[NCELL];
    __shared__ int tmp[1024];

    const int b = blockIdx.x;
    const int t = threadIdx.x;
    const float* X = xyz + (size_t)b * NPTS * 3;

    // folded init: 8 blocks x 1024 threads cover g_Wt + g_scale
    {
        int gid = b * 1024 + t;
        for (int i = gid; i < CIN * COUT; i += BATCH * 1024) {
            int o = i & 255;
            int c = i >> 8;
            g_Wt[c * COUT + o] = W[o * CIN + c];
        }
        if (gid < CIN) g_scale[gid] = gamma[gid] / sqrtf(var[gid] + 1e-5f);
    }

    if (t < NCELL) hist[t] = 0;
    __syncthreads();

    int   cell[NPTS / 1024];
    float px[NPTS / 1024], py[NPTS / 1024], pz[NPTS / 1024];
#pragma unroll
    for (int r = 0; r < NPTS / 1024; r++) {
        int i = t + r * 1024;
        px[r] = X[i * 3 + 0];
        py[r] = X[i * 3 + 1];
        pz[r] = X[i * 3 + 2];
        int cx = (int)(px[r] * 9.99f);
        int cy = (int)(py[r] * 9.99f);
        int cz = (int)(pz[r] * 9.99f);
        cell[r] = (cx * 10 + cy) * 10 + cz;
        atomicAdd(&hist[cell[r]], 1);
    }
    __syncthreads();

    int v = (t < NCELL) ? hist[t] : 0;
    tmp[t] = v;
    __syncthreads();
    for (int d = 1; d < 1024; d <<= 1) {
        int add = (t >= d) ? tmp[t - d] : 0;
        __syncthreads();
        tmp[t] += add;
        __syncthreads();
    }
    if (t < NCELL) {
        int ex = tmp[t] - v;
        off[t] = ex;
        g_cellStart[b * (NCELL + 1) + t] = ex;
    }
    if (t == 0) g_cellStart[b * (NCELL + 1) + NCELL] = NPTS;
    __syncthreads();

#pragma unroll
    for (int r = 0; r < NPTS / 1024; r++) {
        int i = t + r * 1024;
        int pos = atomicAdd(&off[cell[r]], 1);
        g_xyzBin[b * NPTS + pos] = make_float4(px[r], py[r], pz[r], __int_as_float(i));
    }
}

// ---------------- furthest point sampling (R2 exact — frozen) ----------------
__global__ void __launch_bounds__(128, 1) fps_kernel(const float* __restrict__ xyz,
                                                     float* __restrict__ out_xyz) {
    const int b = blockIdx.x;
    const float* X = xyz + (size_t)b * NPTS * 3;
    const int t    = threadIdx.x;
    const int lane = t & 31;
    const int wid  = t >> 5;
    const int base = t * 32;

    u64 PX[16], PY[16], PZ[16];
    float mind[32];
#pragma unroll
    for (int i = 0; i < 16; i++) {
        int p0 = base + 2 * i;
        float x0 = X[p0 * 3 + 0], y0 = X[p0 * 3 + 1], z0 = X[p0 * 3 + 2];
        float x1 = X[p0 * 3 + 3], y1 = X[p0 * 3 + 4], z1 = X[p0 * 3 + 5];
        PX[i] = f2_pack(x0, x1);
        PY[i] = f2_pack(y0, y1);
        PZ[i] = f2_pack(z0, z1);
        mind[2 * i] = 1e10f;
        mind[2 * i + 1] = 1e10f;
    }

    __shared__ u64 s_part[2][4];

    float qx = X[0], qy = X[1], qz = X[2];
    if (t == 0) {
        size_t r = (size_t)(b * NPOINT) * 3;
        g_cent[r + 0] = qx; g_cent[r + 1] = qy; g_cent[r + 2] = qz;
        out_xyz[r + 0] = qx; out_xyz[r + 1] = qy; out_xyz[r + 2] = qz;
    }

    for (int it = 1; it < NPOINT; ++it) {
        const u64 nqx = f2_pack(-qx, -qx);
        const u64 nqy = f2_pack(-qy, -qy);
        const u64 nqz = f2_pack(-qz, -qz);

        unsigned bb = 0u;   // best mind bits (nonneg float -> bits monotonic)
        int bi = 0;
#pragma unroll
        for (int i = 0; i < 16; i++) {
            u64 dx = f2_add(PX[i], nqx);
            u64 dy = f2_add(PY[i], nqy);
            u64 dz = f2_add(PZ[i], nqz);
            u64 s  = f2_add(f2_add(f2_mul(dx, dx), f2_mul(dy, dy)), f2_mul(dz, dz));
            float s0, s1;
            f2_unpack(s, s0, s1);
            mind[2 * i]     = fminf(mind[2 * i], s0);
            mind[2 * i + 1] = fminf(mind[2 * i + 1], s1);
            unsigned m0 = __float_as_uint(mind[2 * i]);
            if (m0 > bb) { bb = m0; bi = base + 2 * i; }       // strict > keeps earliest index
            unsigned m1 = __float_as_uint(mind[2 * i + 1]);
            if (m1 > bb) { bb = m1; bi = base + 2 * i + 1; }
        }

        unsigned wmax = __reduce_max_sync(0xffffffffu, bb);
        unsigned ball = __ballot_sync(0xffffffffu, bb == wmax);
        int src = __ffs(ball) - 1;
        int wbi = __shfl_sync(0xffffffffu, bi, src);
        if (lane == 0)
            s_part[it & 1][wid] = ((u64)wmax << 32) | (unsigned)(~wbi);
        __syncthreads();

        u64 w0 = s_part[it & 1][0];
        u64 w1 = s_part[it & 1][1];
        u64 w2 = s_part[it & 1][2];
        u64 w3 = s_part[it & 1][3];
        u64 win = w0;
        if (w1 > win) win = w1;
        if (w2 > win) win = w2;
        if (w3 > win) win = w3;
        int li = (int)(~(unsigned)win);

        qx = X[li * 3 + 0]; qy = X[li * 3 + 1]; qz = X[li * 3 + 2];
        if (t == 0) {
            size_t r = (size_t)(b * NPOINT + it) * 3;
            g_cent[r + 0] = qx; g_cent[r + 1] = qy; g_cent[r + 2] = qz;
            out_xyz[r + 0] = qx; out_xyz[r + 1] = qy; out_xyz[r + 2] = qz;
        }
    }
}

// ---------------- per-point feature GEMM: P = relu(bn(feat)) @ Wfeat^T ----------------
__global__ void __launch_bounds__(256) gemmP_kernel(const float* __restrict__ feat,
                                                    const float* __restrict__ bn_mean,
                                                    const float* __restrict__ bn_beta) {
    __shared__ float As[16][68];
    __shared__ float Bs[16][68];

    const int bm = blockIdx.x * 64;
    const int bn = blockIdx.y * 64;
    const int tid = threadIdx.x;

    const int row = tid >> 4;
    const int col = tid & 15;
    const int lm  = tid >> 2;
    const int lk4 = (tid & 3) * 4;
    const int kb  = tid >> 4;
    const int nb4 = (tid & 15) * 4;

    float acc[4][4];
#pragma unroll
    for (int i = 0; i < 4; i++)
#pragma unroll
        for (int j = 0; j < 4; j++) acc[i][j] = 0.f;

    for (int k0 = 0; k0 < CFEAT; k0 += 16) {
        float4 a4 = *(const float4*)(feat + (size_t)(bm + lm) * CFEAT + k0 + lk4);
        float av[4] = {a4.x, a4.y, a4.z, a4.w};
#pragma unroll
        for (int i = 0; i < 4; i++) {
            int c = k0 + lk4 + i + 3;
            float v = (av[i] - bn_mean[c]) * g_scale[c] + bn_beta[c];
            As[lk4 + i][lm] = fmaxf(v, 0.f);
        }
        float4 b4 = *(const float4*)(g_Wt + (size_t)(k0 + kb + 3) * COUT + bn + nb4);
        *(float4*)&Bs[kb][nb4] = b4;
        __syncthreads();

#pragma unroll
        for (int k = 0; k < 16; k++) {
            float4 a = *(float4*)&As[k][row * 4];
            float4 bq = *(float4*)&Bs[k][col * 4];
            float ar[4] = {a.x, a.y, a.z, a.w};
            float br[4] = {bq.x, bq.y, bq.z, bq.w};
#pragma unroll
            for (int i = 0; i < 4; i++)
#pragma unroll
                for (int j = 0; j < 4; j++) acc[i][j] += ar[i] * br[j];
        }
        __syncthreads();
    }

#pragma unroll
    for (int i = 0; i < 4; i++) {
        float4 o4 = make_float4(acc[i][0], acc[i][1], acc[i][2], acc[i][3]);
        *(float4*)(g_P + (size_t)(bm + row * 4 + i) * COUT + bn + col * 4) = o4;
    }
}

// ---------------- fused ballq + combine (combine phase vectorized float2) ----------------
__global__ void __launch_bounds__(256) fused_bc_kernel(const float* __restrict__ xyz,
                                                       const float* __restrict__ bias,
                                                       const float* __restrict__ bn_mean,
                                                       const float* __restrict__ bn_beta,
                                                       float* __restrict__ out_feat) {
    __shared__ int   cand[64];
    __shared__ int   sidx[NSAMPLE];
    __shared__ float t0[NSAMPLE], t1[NSAMPLE], t2[NSAMPLE];

    const int g = blockIdx.x;          // 0..8191
    const int b = g >> 10;
    const int s = g & 1023;
    const int t = threadIdx.x;
    const int lane = t & 31;

    if (t < 32) {
        const float cx = g_cent[(size_t)g * 3 + 0];
        const float cy = g_cent[(size_t)g * 3 + 1];
        const float cz = g_cent[(size_t)g * 3 + 2];
        const float4* XB = g_xyzBin + (size_t)b * NPTS;
        const int* CS = g_cellStart + b * (NCELL + 1);
        const float R2 = (float)(0.1 * 0.1);

        int icx = (int)(cx * 9.99f);
        int icy = (int)(cy * 9.99f);
        int icz = (int)(cz * 9.99f);
        int x0 = max(icx - 1, 0), x1 = min(icx + 1, 9);
        int y0 = max(icy - 1, 0), y1 = min(icy + 1, 9);
        int z0 = max(icz - 1, 0), z1 = min(icz + 1, 9);
        int ny = y1 - y0 + 1;
        int nseg = (x1 - x0 + 1) * ny;

        // parallel segment-descriptor fetch: one L2 round-trip instead of 9 serial
        int j0l = 0, j1l = 0;
        if (lane < nseg) {
            int sxi = x0 + lane / ny;
            int syi = y0 + lane % ny;
            int cb = (sxi * 10 + syi) * 10;
            j0l = CS[cb + z0];
            j1l = CS[cb + z1 + 1];
        }

        int cnt = 0;
        for (int sg = 0; sg < nseg; sg++) {
            int j0 = __shfl_sync(0xffffffffu, j0l, sg);
            int j1 = __shfl_sync(0xffffffffu, j1l, sg);
            for (int jj = j0; jj < j1; jj += 32) {
                int j = jj + lane;
                bool valid = false;
                int idx = 0;
                if (j < j1) {
                    float4 p = XB[j];               // coalesced LDG.128
                    idx = __float_as_int(p.w);
                    float dx = __fsub_rn(cx, p.x);
                    float dy = __fsub_rn(cy, p.y);
                    float dz = __fsub_rn(cz, p.z);
                    float d2 = __fadd_rn(__fadd_rn(__fmul_rn(dx, dx), __fmul_rn(dy, dy)),
                                         __fmul_rn(dz, dz));
                    valid = d2 < R2;
                }
                unsigned m = __ballot_sync(0xffffffffu, valid);
                if (valid) {
                    int pos = cnt + __popc(m & ((1u << lane) - 1u));
                    if (pos < 64) cand[pos] = idx;
                }
                cnt += __popc(m);
            }
        }
        __syncwarp();

        int mcnt = cnt < 64 ? cnt : 64;
        int ca = (2 * lane     < mcnt) ? cand[2 * lane]     : SENT;
        int cb2 = (2 * lane + 1 < mcnt) ? cand[2 * lane + 1] : SENT;

        // bitonic sort of 64 ints, 2 per lane, ascending
#pragma unroll
        for (int k = 2; k <= 64; k <<= 1) {
#pragma unroll
            for (int j = k >> 1; j >= 2; j >>= 1) {
                int jl = j >> 1;
                int pa = __shfl_xor_sync(0xffffffffu, ca, jl);
                int pb = __shfl_xor_sync(0xffffffffu, cb2, jl);
                bool up = (((2 * lane) & k) == 0);
                bool lower = ((lane & jl) == 0);
                bool kmin = (up == lower);
                ca = kmin ? min(ca, pa) : max(ca, pa);
                cb2 = kmin ? min(cb2, pb) : max(cb2, pb);
            }
            {   // j == 1: intra-lane pair
                bool up = (((2 * lane) & k) == 0);
                int lo = min(ca, cb2), hi = max(ca, cb2);
                ca = up ? lo : hi;
                cb2 = up ? hi : lo;
            }
        }

        int first = __shfl_sync(0xffffffffu, ca, 0);   // smallest valid index (cnt>=1 always)
        if (lane < 16) {
            int v0 = (ca == SENT) ? first : ca;
            int v1 = (cb2 == SENT) ? first : cb2;
            sidx[2 * lane + 0] = v0;
            sidx[2 * lane + 1] = v1;
#pragma unroll
            for (int r = 0; r < 2; r++) {
                int id = r ? v1 : v0;
                int o2 = 2 * lane + r;
                const float* Xp = xyz + ((size_t)b * NPTS + id) * 3;
                float gx = __fsub_rn(Xp[0], cx);
                float gy = __fsub_rn(Xp[1], cy);
                float gz = __fsub_rn(Xp[2], cz);
                t0[o2] = fmaxf((gx - bn_mean[0]) * g_scale[0] + bn_beta[0], 0.f);
                t1[o2] = fmaxf((gy - bn_mean[1]) * g_scale[1] + bn_beta[1], 0.f);
                t2[o2] = fmaxf((gz - bn_mean[2]) * g_scale[2] + bn_beta[2], 0.f);
            }
        }
    }
    __syncthreads();

    // combine phase: thread t -> cols 2t, 2t+1 (float2 loads; half the LDG count)
    if (t < 128) {
        const float2 w0v = ((const float2*)g_Wt)[t];
        const float2 w1v = ((const float2*)(g_Wt + COUT))[t];
        const float2 w2v = ((const float2*)(g_Wt + 2 * COUT))[t];
        const float2 bv  = ((const float2*)bias)[t];
        const float2* Pb2 = (const float2*)(g_P + (size_t)b * NPTS * COUT);

        float acc0 = -3.402823466e+38f;
        float acc1 = -3.402823466e+38f;
#pragma unroll 8
        for (int k = 0; k < NSAMPLE; k++) {
            float2 pv = Pb2[(size_t)sidx[k] * (COUT / 2) + t];
            float a = t0[k], bq = t1[k], c = t2[k];
            float v0 = fmaf(w0v.x, a, pv.x);
            v0 = fmaf(w1v.x, bq, v0);
            v0 = fmaf(w2v.x, c, v0);
            acc0 = fmaxf(acc0, v0);
            float v1 = fmaf(w0v.y, a, pv.y);
            v1 = fmaf(w1v.y, bq, v1);
            v1 = fmaf(w2v.y, c, v1);
            acc1 = fmaxf(acc1, v1);
        }
        out_feat[((size_t)b * COUT + 2 * t + 0) * NPOINT + s] = acc0 + bv.x;
        out_feat[((size_t)b * COUT + 2 * t + 1) * NPOINT + s] = acc1 + bv.y;
    }
}

// ---------------- launch: side = bin(+init) + gemmP under fps; then fused ballq+combine ----------------
extern "C" void kernel_launch(void* const* d_in, const int* in_sizes, int n_in,
                              void* d_out, int out_size) {
    const float* xyz   = (const float*)d_in[0];
    const float* feat  = (const float*)d_in[1];
    const float* W     = (const float*)d_in[2];
    const float* bias  = (const float*)d_in[3];
    const float* gamma = (const float*)d_in[4];
    const float* beta  = (const float*)d_in[5];
    const float* mean  = (const float*)d_in[6];
    const float* var   = (const float*)d_in[7];

    float* out = (float*)d_out;
    float* out_feat = out + ((size_t)out_size - (size_t)BATCH * COUT * NPOINT);

    cudaStream_t side;
    cudaEvent_t evFork, evJoin;
    cudaStreamCreateWithFlags(&side, cudaStreamNonBlocking);
    cudaEventCreateWithFlags(&evFork, cudaEventDisableTiming);
    cudaEventCreateWithFlags(&evJoin, cudaEventDisableTiming);

    // fork: side branch = bin(+init) then gemmP (hidden under fps)
    cudaEventRecord(evFork, 0);
    cudaStreamWaitEvent(side, evFork, 0);
    bin_kernel<<<BATCH, 1024, 0, side>>>(xyz, W, gamma, var);
    gemmP_kernel<<<dim3((BATCH * NPTS) / 64, COUT / 64), 256, 0, side>>>(feat, mean, beta);
    cudaEventRecord(evJoin, side);

    // main branch: fps, then (after side work) fused ballq+combine
    fps_kernel<<<BATCH, 128>>>(xyz, out);
    cudaStreamWaitEvent(0, evJoin, 0);
    fused_bc_kernel<<<BATCH * NPOINT, 256>>>(xyz, bias, mean, beta, out_feat);
}

// round 15
// speedup vs baseline: 1.2490x; 1.2490x over previous
#include <cuda_runtime.h>
#include <cuda_bf16.h>
#include <cstdint>

#define BATCH 8
#define NPTS  4096
#define CFEAT 128
#define NPOINT 1024
#define NSAMPLE 32
#define COUT  256
#define CIN   131   // 3 + 128
#define NCELL 1000  // 10x10x10
#define SENT  0x7FFFFFFF
#define NTILE 2048              // gemm tiles (512 m-tiles x 4 n-tiles)
#define GEMM_BLKS 140           // persistent gemm blocks (<= non-fps SMs)
#define SMEM_FENCE (120 * 1024) // exclusion fence: fps/gemm own their SMs, L1 keeps 108KB

typedef unsigned long long u64;

// ---------------- scratch (device globals; no allocation allowed) ----------------
__device__ float  g_P[BATCH * NPTS * COUT];          // per-point feature GEMM result
__device__ float  g_cent[BATCH * NPOINT * 3];        // new_xyz copy for device use
__device__ float  g_scale[CIN];                      // gamma / sqrt(var+eps)
__device__ float  g_Wt[CIN * COUT];                  // W transposed
__device__ int    g_cellStart[BATCH * (NCELL + 1)];  // bin CSR offsets
__device__ float4 g_xyzBin[BATCH * NPTS];            // (x,y,z,orig_idx) in binned order

// ---------------- packed f32x2 helpers (bit-identical to scalar rn ops) ----------------
__device__ __forceinline__ u64 f2_add(u64 a, u64 b) {
    u64 r; asm("add.rn.f32x2 %0,%1,%2;" : "=l"(r) : "l"(a), "l"(b)); return r;
}
__device__ __forceinline__ u64 f2_mul(u64 a, u64 b) {
    u64 r; asm("mul.rn.f32x2 %0,%1,%2;" : "=l"(r) : "l"(a), "l"(b)); return r;
}
__device__ __forceinline__ u64 f2_pack(float lo, float hi) {
    u64 r; asm("mov.b64 %0,{%1,%2};" : "=l"(r) : "f"(lo), "f"(hi)); return r;
}
__device__ __forceinline__ void f2_unpack(u64 v, float& lo, float& hi) {
    asm("mov.b64 {%0,%1},%2;" : "=f"(lo), "=f"(hi) : "l"(v));
}

// ---------------- bin points into grid + (folded) init of g_Wt/g_scale ----------------
__global__ void __launch_bounds__(1024) bin_kernel(const float* __restrict__ xyz,
                                                   const float* __restrict__ W,
                                                   const float* __restrict__ gamma,
                                                   const float* __restrict__ var) {
    __shared__ int hist[NCELL];
    __shared__ int off[NCELL];
    __shared__ int tmp[1024];

    const int b = blockIdx.x;
    const int t = threadIdx.x;
    const float* X = xyz + (size_t)b * NPTS * 3;

    // folded init: 8 blocks x 1024 threads cover g_Wt + g_scale
    {
        int gid = b * 1024 + t;
        for (int i = gid; i < CIN * COUT; i += BATCH * 1024) {
            int o = i & 255;
            int c = i >> 8;
            g_Wt[c * COUT + o] = W[o * CIN + c];
        }
        if (gid < CIN) g_scale[gid] = gamma[gid] / sqrtf(var[gid] + 1e-5f);
    }

    if (t < NCELL) hist[t] = 0;
    __syncthreads();

    int   cell[NPTS / 1024];
    float px[NPTS / 1024], py[NPTS / 1024], pz[NPTS / 1024];
#pragma unroll
    for (int r = 0; r < NPTS / 1024; r++) {
        int i = t + r * 1024;
        px[r] = X[i * 3 + 0];
        py[r] = X[i * 3 + 1];
        pz[r] = X[i * 3 + 2];
        int cx = (int)(px[r] * 9.99f);
        int cy = (int)(py[r] * 9.99f);
        int cz = (int)(pz[r] * 9.99f);
        cell[r] = (cx * 10 + cy) * 10 + cz;
        atomicAdd(&hist[cell[r]], 1);
    }
    __syncthreads();

    int v = (t < NCELL) ? hist[t] : 0;
    tmp[t] = v;
    __syncthreads();
    for (int d = 1; d < 1024; d <<= 1) {
        int add = (t >= d) ? tmp[t - d] : 0;
        __syncthreads();
        tmp[t] += add;
        __syncthreads();
    }
    if (t < NCELL) {
        int ex = tmp[t] - v;
        off[t] = ex;
        g_cellStart[b * (NCELL + 1) + t] = ex;
    }
    if (t == 0) g_cellStart[b * (NCELL + 1) + NCELL] = NPTS;
    __syncthreads();

#pragma unroll
    for (int r = 0; r < NPTS / 1024; r++) {
        int i = t + r * 1024;
        int pos = atomicAdd(&off[cell[r]], 1);
        g_xyzBin[b * NPTS + pos] = make_float4(px[r], py[r], pz[r], __int_as_float(i));
    }
}

// ---------------- furthest point sampling (R2 exact — frozen) ----------------
// 120KB unused dynamic smem => exclusive SM (no co-residency tax), L1 keeps 108KB.
__global__ void __launch_bounds__(128, 1) fps_kernel(const float* __restrict__ xyz,
                                                     float* __restrict__ out_xyz) {
    extern __shared__ char fence[];   // unused; occupancy fence
    const int b = blockIdx.x;
    const float* X = xyz + (size_t)b * NPTS * 3;
    const int t    = threadIdx.x;
    const int lane = t & 31;
    const int wid  = t >> 5;
    const int base = t * 32;

    u64 PX[16], PY[16], PZ[16];
    float mind[32];
#pragma unroll
    for (int i = 0; i < 16; i++) {
        int p0 = base + 2 * i;
        float x0 = X[p0 * 3 + 0], y0 = X[p0 * 3 + 1], z0 = X[p0 * 3 + 2];
        float x1 = X[p0 * 3 + 3], y1 = X[p0 * 3 + 4], z1 = X[p0 * 3 + 5];
        PX[i] = f2_pack(x0, x1);
        PY[i] = f2_pack(y0, y1);
        PZ[i] = f2_pack(z0, z1);
        mind[2 * i] = 1e10f;
        mind[2 * i + 1] = 1e10f;
    }

    __shared__ u64 s_part[2][4];

    float qx = X[0], qy = X[1], qz = X[2];
    if (t == 0) {
        size_t r = (size_t)(b * NPOINT) * 3;
        g_cent[r + 0] = qx; g_cent[r + 1] = qy; g_cent[r + 2] = qz;
        out_xyz[r + 0] = qx; out_xyz[r + 1] = qy; out_xyz[r + 2] = qz;
    }

    for (int it = 1; it < NPOINT; ++it) {
        const u64 nqx = f2_pack(-qx, -qx);
        const u64 nqy = f2_pack(-qy, -qy);
        const u64 nqz = f2_pack(-qz, -qz);

        unsigned bb = 0u;   // best mind bits (nonneg float -> bits monotonic)
        int bi = 0;
#pragma unroll
        for (int i = 0; i < 16; i++) {
            u64 dx = f2_add(PX[i], nqx);
            u64 dy = f2_add(PY[i], nqy);
            u64 dz = f2_add(PZ[i], nqz);
            u64 s  = f2_add(f2_add(f2_mul(dx, dx), f2_mul(dy, dy)), f2_mul(dz, dz));
            float s0, s1;
            f2_unpack(s, s0, s1);
            mind[2 * i]     = fminf(mind[2 * i], s0);
            mind[2 * i + 1] = fminf(mind[2 * i + 1], s1);
            unsigned m0 = __float_as_uint(mind[2 * i]);
            if (m0 > bb) { bb = m0; bi = base + 2 * i; }       // strict > keeps earliest index
            unsigned m1 = __float_as_uint(mind[2 * i + 1]);
            if (m1 > bb) { bb = m1; bi = base + 2 * i + 1; }
        }

        unsigned wmax = __reduce_max_sync(0xffffffffu, bb);
        unsigned ball = __ballot_sync(0xffffffffu, bb == wmax);
        int src = __ffs(ball) - 1;
        int wbi = __shfl_sync(0xffffffffu, bi, src);
        if (lane == 0)
            s_part[it & 1][wid] = ((u64)wmax << 32) | (unsigned)(~wbi);
        __syncthreads();

        u64 w0 = s_part[it & 1][0];
        u64 w1 = s_part[it & 1][1];
        u64 w2 = s_part[it & 1][2];
        u64 w3 = s_part[it & 1][3];
        u64 win = w0;
        if (w1 > win) win = w1;
        if (w2 > win) win = w2;
        if (w3 > win) win = w3;
        int li = (int)(~(unsigned)win);

        qx = X[li * 3 + 0]; qy = X[li * 3 + 1]; qz = X[li * 3 + 2];
        if (t == 0) {
            size_t r = (size_t)(b * NPOINT + it) * 3;
            g_cent[r + 0] = qx; g_cent[r + 1] = qy; g_cent[r + 2] = qz;
            out_xyz[r + 0] = qx; out_xyz[r + 1] = qy; out_xyz[r + 2] = qz;
        }
    }
}

// ---------------- persistent per-point GEMM: P = relu(bn(feat)) @ Wfeat^T ----------------
// 140 blocks, 120KB fence => 1 block/SM and NEVER on an fps SM. Loops all tiles.
__global__ void __launch_bounds__(256) gemmP_kernel(const float* __restrict__ feat,
                                                    const float* __restrict__ bn_mean,
                                                    const float* __restrict__ bn_beta) {
    extern __shared__ char fence[];   // unused; occupancy fence
    __shared__ float As[16][68];
    __shared__ float Bs[16][68];

    const int tid = threadIdx.x;
    const int row = tid >> 4;
    const int col = tid & 15;
    const int lm  = tid >> 2;
    const int lk4 = (tid & 3) * 4;
    const int kb  = tid >> 4;
    const int nb4 = (tid & 15) * 4;

    for (int bid = blockIdx.x; bid < NTILE; bid += gridDim.x) {
        const int bm = (bid >> 2) * 64;
        const int bn = (bid & 3) * 64;

        float acc[4][4];
#pragma unroll
        for (int i = 0; i < 4; i++)
#pragma unroll
            for (int j = 0; j < 4; j++) acc[i][j] = 0.f;

        for (int k0 = 0; k0 < CFEAT; k0 += 16) {
            float4 a4 = *(const float4*)(feat + (size_t)(bm + lm) * CFEAT + k0 + lk4);
            float av[4] = {a4.x, a4.y, a4.z, a4.w};
#pragma unroll
            for (int i = 0; i < 4; i++) {
                int c = k0 + lk4 + i + 3;
                float v = (av[i] - bn_mean[c]) * g_scale[c] + bn_beta[c];
                As[lk4 + i][lm] = fmaxf(v, 0.f);
            }
            float4 b4 = *(const float4*)(g_Wt + (size_t)(k0 + kb + 3) * COUT + bn + nb4);
            *(float4*)&Bs[kb][nb4] = b4;
            __syncthreads();

#pragma unroll
            for (int k = 0; k < 16; k++) {
                float4 a = *(float4*)&As[k][row * 4];
                float4 bq = *(float4*)&Bs[k][col * 4];
                float ar[4] = {a.x, a.y, a.z, a.w};
                float br[4] = {bq.x, bq.y, bq.z, bq.w};
#pragma unroll
                for (int i = 0; i < 4; i++)
#pragma unroll
                    for (int j = 0; j < 4; j++) acc[i][j] += ar[i] * br[j];
            }
            __syncthreads();
        }

#pragma unroll
        for (int i = 0; i < 4; i++) {
            float4 o4 = make_float4(acc[i][0], acc[i][1], acc[i][2], acc[i][3]);
            *(float4*)(g_P + (size_t)(bm + row * 4 + i) * COUT + bn + col * 4) = o4;
        }
    }
}

// ---------------- fused ballq + combine (R13 scalar combine — proven) ----------------
__global__ void __launch_bounds__(256) fused_bc_kernel(const float* __restrict__ xyz,
                                                       const float* __restrict__ bias,
                                                       const float* __restrict__ bn_mean,
                                                       const float* __restrict__ bn_beta,
                                                       float* __restrict__ out_feat) {
    __shared__ int   cand[64];
    __shared__ int   sidx[NSAMPLE];
    __shared__ float t0[NSAMPLE], t1[NSAMPLE], t2[NSAMPLE];

    const int g = blockIdx.x;          // 0..8191
    const int b = g >> 10;
    const int s = g & 1023;
    const int t = threadIdx.x;
    const int lane = t & 31;

    if (t < 32) {
        const float cx = g_cent[(size_t)g * 3 + 0];
        const float cy = g_cent[(size_t)g * 3 + 1];
        const float cz = g_cent[(size_t)g * 3 + 2];
        const float4* XB = g_xyzBin + (size_t)b * NPTS;
        const int* CS = g_cellStart + b * (NCELL + 1);
        const float R2 = (float)(0.1 * 0.1);

        int icx = (int)(cx * 9.99f);
        int icy = (int)(cy * 9.99f);
        int icz = (int)(cz * 9.99f);
        int x0 = max(icx - 1, 0), x1 = min(icx + 1, 9);
        int y0 = max(icy - 1, 0), y1 = min(icy + 1, 9);
        int z0 = max(icz - 1, 0), z1 = min(icz + 1, 9);
        int ny = y1 - y0 + 1;
        int nseg = (x1 - x0 + 1) * ny;

        // parallel segment-descriptor fetch: one L2 round-trip instead of 9 serial
        int j0l = 0, j1l = 0;
        if (lane < nseg) {
            int sxi = x0 + lane / ny;
            int syi = y0 + lane % ny;
            int cb = (sxi * 10 + syi) * 10;
            j0l = CS[cb + z0];
            j1l = CS[cb + z1 + 1];
        }

        int cnt = 0;
        for (int sg = 0; sg < nseg; sg++) {
            int j0 = __shfl_sync(0xffffffffu, j0l, sg);
            int j1 = __shfl_sync(0xffffffffu, j1l, sg);
            for (int jj = j0; jj < j1; jj += 32) {
                int j = jj + lane;
                bool valid = false;
                int idx = 0;
                if (j < j1) {
                    float4 p = XB[j];               // coalesced LDG.128
                    idx = __float_as_int(p.w);
                    float dx = __fsub_rn(cx, p.x);
                    float dy = __fsub_rn(cy, p.y);
                    float dz = __fsub_rn(cz, p.z);
                    float d2 = __fadd_rn(__fadd_rn(__fmul_rn(dx, dx), __fmul_rn(dy, dy)),
                                         __fmul_rn(dz, dz));
                    valid = d2 < R2;
                }
                unsigned m = __ballot_sync(0xffffffffu, valid);
                if (valid) {
                    int pos = cnt + __popc(m & ((1u << lane) - 1u));
                    if (pos < 64) cand[pos] = idx;
                }
                cnt += __popc(m);
            }
        }
        __syncwarp();

        int mcnt = cnt < 64 ? cnt : 64;
        int ca = (2 * lane     < mcnt) ? cand[2 * lane]     : SENT;
        int cb2 = (2 * lane + 1 < mcnt) ? cand[2 * lane + 1] : SENT;

        // bitonic sort of 64 ints, 2 per lane, ascending
#pragma unroll
        for (int k = 2; k <= 64; k <<= 1) {
#pragma unroll
            for (int j = k >> 1; j >= 2; j >>= 1) {
                int jl = j >> 1;
                int pa = __shfl_xor_sync(0xffffffffu, ca, jl);
                int pb = __shfl_xor_sync(0xffffffffu, cb2, jl);
                bool up = (((2 * lane) & k) == 0);
                bool lower = ((lane & jl) == 0);
                bool kmin = (up == lower);
                ca = kmin ? min(ca, pa) : max(ca, pa);
                cb2 = kmin ? min(cb2, pb) : max(cb2, pb);
            }
            {   // j == 1: intra-lane pair
                bool up = (((2 * lane) & k) == 0);
                int lo = min(ca, cb2), hi = max(ca, cb2);
                ca = up ? lo : hi;
                cb2 = up ? hi : lo;
            }
        }

        int first = __shfl_sync(0xffffffffu, ca, 0);   // smallest valid index (cnt>=1 always)
        if (lane < 16) {
            int v0 = (ca == SENT) ? first : ca;
            int v1 = (cb2 == SENT) ? first : cb2;
            sidx[2 * lane + 0] = v0;
            sidx[2 * lane + 1] = v1;
#pragma unroll
            for (int r = 0; r < 2; r++) {
                int id = r ? v1 : v0;
                int o2 = 2 * lane + r;
                const float* Xp = xyz + ((size_t)b * NPTS + id) * 3;
                float gx = __fsub_rn(Xp[0], cx);
                float gy = __fsub_rn(Xp[1], cy);
                float gz = __fsub_rn(Xp[2], cz);
                t0[o2] = fmaxf((gx - bn_mean[0]) * g_scale[0] + bn_beta[0], 0.f);
                t1[o2] = fmaxf((gy - bn_mean[1]) * g_scale[1] + bn_beta[1], 0.f);
                t2[o2] = fmaxf((gz - bn_mean[2]) * g_scale[2] + bn_beta[2], 0.f);
            }
        }
    }
    __syncthreads();

    const int o = t;
    const float w0 = g_Wt[0 * COUT + o];
    const float w1 = g_Wt[1 * COUT + o];
    const float w2 = g_Wt[2 * COUT + o];
    const float* Pb = g_P + (size_t)b * NPTS * COUT;

    float acc = -3.402823466e+38f;
#pragma unroll 8
    for (int k = 0; k < NSAMPLE; k++) {
        float v = Pb[(size_t)sidx[k] * COUT + o];
        v = fmaf(w0, t0[k], v);
        v = fmaf(w1, t1[k], v);
        v = fmaf(w2, t2[k], v);
        acc = fmaxf(acc, v);
    }
    out_feat[((size_t)b * COUT + o) * NPOINT + s] = acc + bias[o];
}

// ---------------- launch: bin -> { fps (fenced) || gemm (fenced persistent) } -> fused_bc ----------------
extern "C" void kernel_launch(void* const* d_in, const int* in_sizes, int n_in,
                              void* d_out, int out_size) {
    const float* xyz   = (const float*)d_in[0];
    const float* feat  = (const float*)d_in[1];
    const float* W     = (const float*)d_in[2];
    const float* bias  = (const float*)d_in[3];
    const float* gamma = (const float*)d_in[4];
    const float* beta  = (const float*)d_in[5];
    const float* mean  = (const float*)d_in[6];
    const float* var   = (const float*)d_in[7];

    float* out = (float*)d_out;
    float* out_feat = out + ((size_t)out_size - (size_t)BATCH * COUT * NPOINT);

    cudaFuncSetAttribute(fps_kernel, cudaFuncAttributeMaxDynamicSharedMemorySize,
                         SMEM_FENCE);
    cudaFuncSetAttribute(gemmP_kernel, cudaFuncAttributeMaxDynamicSharedMemorySize,
                         SMEM_FENCE);

    cudaStream_t side;
    cudaEvent_t evFork, evJoin;
    cudaStreamCreateWithFlags(&side, cudaStreamNonBlocking);
    cudaEventCreateWithFlags(&evFork, cudaEventDisableTiming);
    cudaEventCreateWithFlags(&evJoin, cudaEventDisableTiming);

    // bin (with folded init) runs first on an empty chip
    bin_kernel<<<BATCH, 1024>>>(xyz, W, gamma, var);

    // fork: fps on main (8 exclusive SMs), persistent gemm on side (140 exclusive SMs)
    cudaEventRecord(evFork, 0);
    cudaStreamWaitEvent(side, evFork, 0);
    fps_kernel<<<BATCH, 128, SMEM_FENCE>>>(xyz, out);
    gemmP_kernel<<<GEMM_BLKS, 256, SMEM_FENCE, side>>>(feat, mean, beta);
    cudaEventRecord(evJoin, side);

    // join: fused ballq+combine needs fps + gemm + bin
    cudaStreamWaitEvent(0, evJoin, 0);
    fused_bc_kernel<<<BATCH * NPOINT, 256>>>(xyz, bias, mean, beta, out_feat);
}